// round 13
// baseline (speedup 1.0000x reference)
#include <cuda_runtime.h>
#include <cuda_bf16.h>
#include <cstdint>

// Problem dims (fixed by the dataset)
#define Bz 32
#define Tz 1000
#define Hz 512
#define Vz 2048
#define Lz 100
#define BTz (Bz*Tz)
#define Sz (2*Lz+1)           // 201
#define NLAB 101              // blank + L labels
#define NEGINF (-1e10f)
#define CCOMP 5.0f            // per-step decay compensation (probs stored * e^C)
#define LN2F 0.69314718055994531f

// ---------------- device scratch (static: no allocation) ----------------
__device__ __nv_bfloat16 g_Wbf[Vz*Hz];         // W in bf16 (2 MB)
__device__ __nv_bfloat16 g_Wlab[Bz*128*Hz];    // gathered label W rows (padded to 128)
__device__ float         g_blab[Bz*128];       // gathered label biases
__device__ float         g_lab[(size_t)BTz*NLAB]; // label probs * e^C
__device__ float         g_lossb[Bz];

// ---------------- helpers ----------------
__device__ __forceinline__ void mma16816(float* c, uint32_t a0, uint32_t a1,
                                         uint32_t a2, uint32_t a3,
                                         uint32_t b0, uint32_t b1) {
    asm volatile(
        "mma.sync.aligned.m16n8k16.row.col.f32.bf16.bf16.f32 "
        "{%0,%1,%2,%3}, {%4,%5,%6,%7}, {%8,%9}, {%0,%1,%2,%3};\n"
        : "+f"(c[0]), "+f"(c[1]), "+f"(c[2]), "+f"(c[3])
        : "r"(a0), "r"(a1), "r"(a2), "r"(a3), "r"(b0), "r"(b1));
}
__device__ __forceinline__ float exp2i(int j) {   // exact 2^j; 0 below 2^-126
    if (j < -126) return 0.f;
    if (j > 127)  j = 127;
    return __uint_as_float((uint32_t)(127 + j) << 23);
}

#define A_STR 520   // bf16 elems per A smem row (512 + 8 pad -> conflict-free LDS)
#define W_STR 72    // bf16 elems per W smem row (64 + 8 pad)
#define A_BYTES  (128*A_STR*2)                  // 133120
#define W2_BYTES (2*128*W_STR*2)                // 36864
#define BIAS_OFF (A_BYTES + W2_BYTES)           // 169984
#define SL_OFF   (BIAS_OFF + Vz*4)              // 178176
#define MAIN_SMEM (SL_OFF + 2*128*8)            // 180224

// ---------------- kernel 1: fp32 -> bf16 conversion (W only) ----------------
__global__ void k_convertW(const float* __restrict__ Wm) {
    const int nW2 = (Vz*Hz)/2;
    __nv_bfloat162* W2 = reinterpret_cast<__nv_bfloat162*>(g_Wbf);
    const float2* w2 = reinterpret_cast<const float2*>(Wm);
    for (int i = blockIdx.x*blockDim.x + threadIdx.x; i < nW2; i += gridDim.x*blockDim.x) {
        float2 v = w2[i]; W2[i] = __floats2bfloat162_rn(v.x, v.y);
    }
}

// ---------------- kernel 2: gather label W rows + biases ----------------
__global__ void k_gather(const float* __restrict__ bias, const int* __restrict__ ys) {
    int idx = blockIdx.x;            // b*128 + j
    int b = idx >> 7, j = idx & 127;
    int v = (j == 0) ? 0 : ((j <= Lz) ? ys[b*Lz + j - 1] : -1);
    uint4* dst = reinterpret_cast<uint4*>(g_Wlab + (size_t)idx*Hz);
    if (v >= 0) {
        const uint4* src = reinterpret_cast<const uint4*>(g_Wbf + (size_t)v*Hz);
        dst[threadIdx.x] = src[threadIdx.x];
    } else {
        dst[threadIdx.x] = make_uint4(0u,0u,0u,0u);
    }
    if (threadIdx.x == 0) g_blab[idx] = (v >= 0) ? bias[v] : 0.f;
}

// ---------------- kernel 3: fused GEMM + online LSE + label probs ----------------
// (unchanged from round-11 best)
__global__ __launch_bounds__(256, 1) void k_main(const float* __restrict__ eouts,
                                                 const float* __restrict__ bias) {
    extern __shared__ char smc[];
    __nv_bfloat16* As = reinterpret_cast<__nv_bfloat16*>(smc);
    __nv_bfloat16* Ws = As + 128*A_STR;
    float*  bias_s = reinterpret_cast<float*>(smc + BIAS_OFF);
    float2* sL     = reinterpret_cast<float2*>(smc + SL_OFF);
    const int tid = threadIdx.x;
    const int w = tid >> 5, lane = tid & 31, g = lane >> 2, tig = lane & 3;
    const int wm = w >> 1, wn = w & 1;
    const int rA0 = wm*32 + g;       // base row (of 4: rA0+8i)
    const int nb  = wn*64;           // base col within chunk
    const int b  = blockIdx.x >> 3;
    const int t0 = (blockIdx.x & 7) * 125;

    for (int i = tid; i < Vz/4; i += 256)
        reinterpret_cast<float4*>(bias_s)[i] = reinterpret_cast<const float4*>(bias)[i];

    // A tile: 128 rows x 512, fp32 -> bf16 inline, clamped t
    for (int e = tid; e < 128*64; e += 256) {
        int row = e >> 6, c = e & 63;
        int t = t0 + row; if (t > Tz-1) t = Tz-1;
        const float4* src = reinterpret_cast<const float4*>(eouts + (size_t)(b*Tz + t)*Hz + c*8);
        float4 v0 = src[0], v1 = src[1];
        __nv_bfloat162 p0 = __floats2bfloat162_rn(v0.x, v0.y);
        __nv_bfloat162 p1 = __floats2bfloat162_rn(v0.z, v0.w);
        __nv_bfloat162 p2 = __floats2bfloat162_rn(v1.x, v1.y);
        __nv_bfloat162 p3 = __floats2bfloat162_rn(v1.z, v1.w);
        uint4 pk = make_uint4(*reinterpret_cast<uint32_t*>(&p0), *reinterpret_cast<uint32_t*>(&p1),
                              *reinterpret_cast<uint32_t*>(&p2), *reinterpret_cast<uint32_t*>(&p3));
        *reinterpret_cast<uint4*>(As + row*A_STR + c*8) = pk;
    }

    float M[4] = {-3e38f,-3e38f,-3e38f,-3e38f};
    float S[4] = {0.f,0.f,0.f,0.f};
    float lsev[4];

    #pragma unroll 1
    for (int nc = 0; nc < 17; nc++) {
        if (nc == 16) {
            if (tig == 0) {
                #pragma unroll
                for (int i = 0; i < 4; i++)
                    sL[wn*128 + rA0 + 8*i] = make_float2(M[i], S[i]);
            }
            __syncthreads();
            #pragma unroll
            for (int i = 0; i < 4; i++) {
                float2 o = sL[(wn^1)*128 + rA0 + 8*i];
                float mn = fmaxf(M[i], o.x);
                float ss = S[i]*__expf(M[i]-mn) + o.y*__expf(o.x-mn);
                lsev[i] = mn + __logf(ss);
            }
        }
        const __nv_bfloat16* wsrc = (nc < 16) ? (g_Wbf + (size_t)(nc*128)*Hz)
                                              : (g_Wlab + (size_t)b*128*Hz);
        uint2 rg[8];
        #pragma unroll
        for (int q = 0; q < 8; q++) {
            int e = tid + q*256; int row = e >> 4, c = e & 15;
            rg[q] = *reinterpret_cast<const uint2*>(wsrc + (size_t)row*Hz + c*4);
        }
        #pragma unroll
        for (int q = 0; q < 8; q++) {
            int e = tid + q*256; int row = e >> 4, c = e & 15;
            *reinterpret_cast<uint2*>(Ws + row*W_STR + c*4) = rg[q];
        }
        __syncthreads();

        float acc[2][8][4];
        #pragma unroll
        for (int mt = 0; mt < 2; mt++)
            #pragma unroll
            for (int nt = 0; nt < 8; nt++) {
                acc[mt][nt][0]=0.f; acc[mt][nt][1]=0.f; acc[mt][nt][2]=0.f; acc[mt][nt][3]=0.f;
            }

        #pragma unroll 1
        for (int kc = 0; kc < 8; kc++) {
            if (kc < 7) {
                #pragma unroll
                for (int q = 0; q < 8; q++) {
                    int e = tid + q*256; int row = e >> 4, c = e & 15;
                    rg[q] = *reinterpret_cast<const uint2*>(wsrc + (size_t)row*Hz + (kc+1)*64 + c*4);
                }
            }
            const __nv_bfloat16* Wb = Ws + (kc & 1) * (128*W_STR);
            #pragma unroll
            for (int ks = 0; ks < 4; ks++) {
                const int kk = kc*64 + ks*16;
                uint32_t a0[2], a1[2], a2[2], a3[2];
                #pragma unroll
                for (int mt = 0; mt < 2; mt++) {
                    const int R = rA0 + 16*mt;
                    a0[mt] = *reinterpret_cast<const uint32_t*>(As + R*A_STR + kk + 2*tig);
                    a1[mt] = *reinterpret_cast<const uint32_t*>(As + (R+8)*A_STR + kk + 2*tig);
                    a2[mt] = *reinterpret_cast<const uint32_t*>(As + R*A_STR + kk + 8 + 2*tig);
                    a3[mt] = *reinterpret_cast<const uint32_t*>(As + (R+8)*A_STR + kk + 8 + 2*tig);
                }
                #pragma unroll
                for (int nt = 0; nt < 8; nt++) {
                    uint32_t b0 = *reinterpret_cast<const uint32_t*>(Wb + (nb+nt*8+g)*W_STR + ks*16 + 2*tig);
                    uint32_t b1 = *reinterpret_cast<const uint32_t*>(Wb + (nb+nt*8+g)*W_STR + ks*16 + 8 + 2*tig);
                    mma16816(acc[0][nt], a0[0], a1[0], a2[0], a3[0], b0, b1);
                    mma16816(acc[1][nt], a0[1], a1[1], a2[1], a3[1], b0, b1);
                }
            }
            __syncthreads();
            if (kc < 7) {
                __nv_bfloat16* Wd = Ws + ((kc+1) & 1) * (128*W_STR);
                #pragma unroll
                for (int q = 0; q < 8; q++) {
                    int e = tid + q*256; int row = e >> 4, c = e & 15;
                    *reinterpret_cast<uint2*>(Wd + row*W_STR + c*4) = rg[q];
                }
                __syncthreads();
            }
        }

        if (nc < 16) {
            float bm[4] = {-3e38f,-3e38f,-3e38f,-3e38f};
            #pragma unroll
            for (int nt = 0; nt < 8; nt++) {
                int c0 = nc*128 + nb + nt*8 + 2*tig;
                float bb0 = bias_s[c0], bb1 = bias_s[c0+1];
                #pragma unroll
                for (int mt = 0; mt < 2; mt++) {
                    acc[mt][nt][0]+=bb0; acc[mt][nt][1]+=bb1;
                    acc[mt][nt][2]+=bb0; acc[mt][nt][3]+=bb1;
                    bm[2*mt]   = fmaxf(bm[2*mt],   fmaxf(acc[mt][nt][0], acc[mt][nt][1]));
                    bm[2*mt+1] = fmaxf(bm[2*mt+1], fmaxf(acc[mt][nt][2], acc[mt][nt][3]));
                }
            }
            float bs[4] = {0.f,0.f,0.f,0.f};
            #pragma unroll
            for (int nt = 0; nt < 8; nt++)
                #pragma unroll
                for (int mt = 0; mt < 2; mt++) {
                    bs[2*mt]   += __expf(acc[mt][nt][0]-bm[2*mt])   + __expf(acc[mt][nt][1]-bm[2*mt]);
                    bs[2*mt+1] += __expf(acc[mt][nt][2]-bm[2*mt+1]) + __expf(acc[mt][nt][3]-bm[2*mt+1]);
                }
            #pragma unroll
            for (int off = 1; off <= 2; off <<= 1) {
                #pragma unroll
                for (int i = 0; i < 4; i++) {
                    float mo = __shfl_xor_sync(0xffffffffu, bm[i], off);
                    float so = __shfl_xor_sync(0xffffffffu, bs[i], off);
                    float mn = fmaxf(bm[i], mo);
                    bs[i] = bs[i]*__expf(bm[i]-mn) + so*__expf(mo-mn); bm[i] = mn;
                }
            }
            #pragma unroll
            for (int i = 0; i < 4; i++) {
                float mn = fmaxf(M[i], bm[i]);
                S[i] = S[i]*__expf(M[i]-mn) + bs[i]*__expf(bm[i]-mn); M[i] = mn;
            }
        } else {
            // label epilogue: store p' = exp(logit + blab - lse + C)
            #pragma unroll
            for (int i = 0; i < 4; i++) {
                int R = rA0 + 8*i;
                int t = t0 + R; if (t > Tz-1) t = Tz-1;
                float* ptr = g_lab + (size_t)(b*Tz + t)*NLAB;
                const int mt = i >> 1, q = (i & 1)*2;
                #pragma unroll
                for (int nt = 0; nt < 8; nt++) {
                    int c0 = nb + nt*8 + 2*tig;
                    if (c0 < NLAB)
                        ptr[c0]   = __expf(acc[mt][nt][q]   + g_blab[b*128 + c0]   - lsev[i] + CCOMP);
                    if (c0+1 < NLAB)
                        ptr[c0+1] = __expf(acc[mt][nt][q+1] + g_blab[b*128 + c0+1] - lsev[i] + CCOMP);
                }
            }
        }
    }
}

// ---------------- kernel 4: CTC forward DP (linear, per-warp exponents, 8-deep prefetch) ----
// 7 warps x 64 states (32 own + 32 left halo), interleaved (even,odd) per lane.
// Step = shfl + adds + mults (no MUFU). 8-deep label prefetch (one slot per step
// of the unrolled block; issue-to-use distance ~300 cyc > L2 latency).
// Every 8 steps: redux-max -> per-warp rescale to 2^30; halo import with exact
// power-of-two reconciliation. Double-buffered smem -> ONE barrier per exchange.
__global__ __launch_bounds__(224) void k_dp(const int* __restrict__ ys,
                                            const int* __restrict__ elens,
                                            const int* __restrict__ ylens) {
    __shared__ float sA[2][224];
    __shared__ int   sE[2][8];
    __shared__ int   sM[2][8];
    const int SENT = -(1 << 29);
    const int b = blockIdx.x;
    const int tid = threadIdx.x, w = tid >> 5, lane = tid & 31;
    const int elen = elens[b], ylen = ylens[b];
    const int smax = 2*ylen + 1;
    const int s0 = 32*w - 32 + 2*lane;
    const int s1 = s0 + 1;
    const bool v0 = (s0 >= 0) && (s0 < smax);
    const bool v1 = (s1 >= 0) && (s1 < smax);
    const int yidx = (s1 >= 1) ? (s1 >> 1) : 0;
    const int j1c  = min(max(yidx + 1, 0), NLAB - 1);
    bool skip1 = false;
    if (s1 >= 3 && yidx >= 1 && yidx <= Lz - 1)
        skip1 = (ys[b*Lz + yidx] != ys[b*Lz + yidx - 1]);
    const float* lab = g_lab + (size_t)b*Tz*NLAB;

    float r0 = (v0 && s0 == 0) ? __ldg(lab + 0) : 0.f;
    float r1 = (v1 && s1 == 1) ? __ldg(lab + 1) : 0.f;

    // 8-deep prefetch: slot d holds probs for the d-th step of the current block
    float pB[8], p1[8];
    #pragma unroll
    for (int d = 0; d < 8; d++) {
        int tt = 1 + d; if (tt > elen-1) tt = elen-1;
        const float* q = lab + (size_t)tt * NLAB;
        pB[d] = __ldg(q);
        p1[d] = __ldg(q + j1c);
    }

    int Ew = 0;
    int buf = 0;

    int t = 1;
    while (t < elen) {
        const int rem = elen - t;
        if (rem >= 8) {
            #pragma unroll
            for (int i = 0; i < 8; i++) {
                float r1m = __shfl_up_sync(0xffffffffu, r1, 1);
                if (lane == 0) r1m = 0.f;
                float n0 = (r0 + r1m) * pB[i];
                float x2 = skip1 ? r1m : 0.f;
                float n1 = (r1 + r0 + x2) * p1[i];
                r0 = v0 ? n0 : 0.f;
                r1 = v1 ? n1 : 0.f;
                // refill slot i for the same position in the NEXT block (t+i+8)
                int tn = t + i + 8; if (tn > elen-1) tn = elen-1;
                const float* q = lab + (size_t)tn * NLAB;
                pB[i] = __ldg(q);
                p1[i] = __ldg(q + j1c);
            }
            t += 8;
        } else {
            #pragma unroll
            for (int i = 0; i < 8; i++) {
                if (i < rem) {
                    float r1m = __shfl_up_sync(0xffffffffu, r1, 1);
                    if (lane == 0) r1m = 0.f;
                    float n0 = (r0 + r1m) * pB[i];
                    float x2 = skip1 ? r1m : 0.f;
                    float n1 = (r1 + r0 + x2) * p1[i];
                    r0 = v0 ? n0 : 0.f;
                    r1 = v1 ? n1 : 0.f;
                }
            }
            t += rem;
        }
        // exchange: redux max (positive floats order as uints) + publish + ONE barrier
        uint32_t lmu;
        {
            float lmf = fmaxf(r0, r1);
            asm volatile("redux.sync.max.u32 %0, %1, 0xffffffff;"
                         : "=r"(lmu) : "r"(__float_as_uint(lmf)));
        }
        if (lane >= 16) { sA[buf][s0] = r0; sA[buf][s1] = r1; }
        if (lane == 0) {
            sE[buf][w] = Ew;
            sM[buf][w] = (lmu != 0u)
                ? (Ew + (int)((lmu >> 23) & 0xFFu) - 127)
                : SENT;
        }
        __syncthreads();
        const int eown = sM[buf][w];
        const int enbr = (w > 0) ? sM[buf][w-1] : SENT;
        const int Enbr_old = (w > 0) ? sE[buf][w-1] : 0;
        const int etop = (eown > enbr) ? eown : enbr;
        if (etop > SENT) {
            const int Enew = etop - 30;                    // warp max -> 2^30
            int kk = Ew - Enew;
            float h0 = r0, h1 = r1;
            if (lane < 16 && w > 0) {                      // halo import at nbr scale
                h0 = sA[buf][s0]; h1 = sA[buf][s1]; kk = Enbr_old - Enew;
            }
            const int k1 = kk >> 1, k2 = kk - (kk >> 1);   // exact two-factor 2^kk
            const float f1 = exp2i(k1), f2 = exp2i(k2);
            r0 = h0 * f1 * f2;
            r1 = h1 * f1 * f2;
            Ew = Enew;
        } else {
            if (lane < 16 && w > 0) { r0 = sA[buf][s0]; r1 = sA[buf][s1]; }
        }
        buf ^= 1;          // next exchange writes the other buffer (no 2nd barrier)
    }

    // final publish with per-warp exponents
    if (lane >= 16) { sA[buf][s0] = r0; sA[buf][s1] = r1; }
    if (lane == 0) sE[buf][w] = Ew;
    __syncthreads();
    if (tid == 0) {
        const int ya = 2*ylen;
        float a = sA[buf][ya], c = sA[buf][ya - 1];
        int  Ea = sE[buf][ya >> 5], Ec = sE[buf][(ya - 1) >> 5];
        float La = (a > 0.f) ? (__logf(a) + (float)Ea * LN2F) : -3e38f;
        float Lc = (c > 0.f) ? (__logf(c) + (float)Ec * LN2F) : -3e38f;
        float m = fmaxf(La, Lc);
        float loss;
        if (m < -1e37f) loss = 1e30f;
        else loss = CCOMP * (float)elen - (m + __logf(__expf(La - m) + __expf(Lc - m)));
        g_lossb[b] = (loss < -0.5f*NEGINF) ? loss : 0.f;
    }
}

// ---------------- kernel 5: deterministic finalize ----------------
__global__ void k_final(float* __restrict__ out) {
    if (threadIdx.x == 0 && blockIdx.x == 0) {
        float s = 0.f;
        for (int b = 0; b < Bz; b++) s += g_lossb[b];
        out[0] = s / (float)Bz;
    }
}

// ---------------- entry ----------------
extern "C" void kernel_launch(void* const* d_in, const int* in_sizes, int n_in,
                              void* d_out, int out_size) {
    const float* eouts = (const float*)d_in[0];
    const float* W     = (const float*)d_in[1];
    const float* bias  = (const float*)d_in[2];
    const int*   ys    = (const int*)d_in[3];
    const int*   elens = (const int*)d_in[4];
    const int*   ylens = (const int*)d_in[5];
    float* out = (float*)d_out;

    cudaFuncSetAttribute(k_main, cudaFuncAttributeMaxDynamicSharedMemorySize, MAIN_SMEM);

    k_convertW<<<256, 256>>>(W);
    k_gather<<<Bz*128, 64>>>(bias, ys);
    k_main<<<Bz*8, 256, MAIN_SMEM>>>(eouts, bias);
    k_dp<<<Bz, 224>>>(ys, elens, ylens);
    k_final<<<1, 32>>>(out);
}

// round 16
// speedup vs baseline: 1.1101x; 1.1101x over previous
#include <cuda_runtime.h>
#include <cuda_bf16.h>
#include <cstdint>

// Problem dims (fixed by the dataset)
#define Bz 32
#define Tz 1000
#define Hz 512
#define Vz 2048
#define Lz 100
#define BTz (Bz*Tz)
#define Sz (2*Lz+1)           // 201
#define NLAB 101              // blank + L labels
#define NEGINF (-1e10f)
#define CCOMP 5.0f            // per-step decay compensation (probs stored * e^C)
#define LN2F 0.69314718055994531f

// ---------------- device scratch (static: no allocation) ----------------
__device__ __nv_bfloat16 g_Wbf[Vz*Hz];         // W in bf16 (2 MB)
__device__ __nv_bfloat16 g_Wlab[Bz*128*Hz];    // gathered label W rows (padded to 128)
__device__ float         g_blab[Bz*128];       // gathered label biases
__device__ float         g_lab[(size_t)BTz*NLAB]; // label probs * e^C
__device__ float         g_fa[Bz*224];         // forward alpha at Tm
__device__ float         g_ba[Bz*224];         // backward beta at Tm
__device__ int           g_faE[Bz*8];          // forward per-warp exponents
__device__ int           g_baE[Bz*8];          // backward per-warp exponents
__device__ float         g_lossb[Bz];

// ---------------- helpers ----------------
__device__ __forceinline__ void mma16816(float* c, uint32_t a0, uint32_t a1,
                                         uint32_t a2, uint32_t a3,
                                         uint32_t b0, uint32_t b1) {
    asm volatile(
        "mma.sync.aligned.m16n8k16.row.col.f32.bf16.bf16.f32 "
        "{%0,%1,%2,%3}, {%4,%5,%6,%7}, {%8,%9}, {%0,%1,%2,%3};\n"
        : "+f"(c[0]), "+f"(c[1]), "+f"(c[2]), "+f"(c[3])
        : "r"(a0), "r"(a1), "r"(a2), "r"(a3), "r"(b0), "r"(b1));
}
__device__ __forceinline__ float exp2i(int j) {   // exact 2^j; 0 below 2^-126
    if (j < -126) return 0.f;
    if (j > 127)  j = 127;
    return __uint_as_float((uint32_t)(127 + j) << 23);
}

#define A_STR 520
#define W_STR 72
#define A_BYTES  (128*A_STR*2)
#define W2_BYTES (2*128*W_STR*2)
#define BIAS_OFF (A_BYTES + W2_BYTES)
#define SL_OFF   (BIAS_OFF + Vz*4)
#define MAIN_SMEM (SL_OFF + 2*128*8)

// ---------------- kernel 1: fp32 -> bf16 conversion (W only) ----------------
__global__ void k_convertW(const float* __restrict__ Wm) {
    const int nW2 = (Vz*Hz)/2;
    __nv_bfloat162* W2 = reinterpret_cast<__nv_bfloat162*>(g_Wbf);
    const float2* w2 = reinterpret_cast<const float2*>(Wm);
    for (int i = blockIdx.x*blockDim.x + threadIdx.x; i < nW2; i += gridDim.x*blockDim.x) {
        float2 v = w2[i]; W2[i] = __floats2bfloat162_rn(v.x, v.y);
    }
}

// ---------------- kernel 2: gather label W rows + biases ----------------
__global__ void k_gather(const float* __restrict__ bias, const int* __restrict__ ys) {
    int idx = blockIdx.x;            // b*128 + j
    int b = idx >> 7, j = idx & 127;
    int v = (j == 0) ? 0 : ((j <= Lz) ? ys[b*Lz + j - 1] : -1);
    uint4* dst = reinterpret_cast<uint4*>(g_Wlab + (size_t)idx*Hz);
    if (v >= 0) {
        const uint4* src = reinterpret_cast<const uint4*>(g_Wbf + (size_t)v*Hz);
        dst[threadIdx.x] = src[threadIdx.x];
    } else {
        dst[threadIdx.x] = make_uint4(0u,0u,0u,0u);
    }
    if (threadIdx.x == 0) g_blab[idx] = (v >= 0) ? bias[v] : 0.f;
}

// ---------------- kernel 3: fused GEMM + online LSE + label probs (proven) ----------------
__global__ __launch_bounds__(256, 1) void k_main(const float* __restrict__ eouts,
                                                 const float* __restrict__ bias) {
    extern __shared__ char smc[];
    __nv_bfloat16* As = reinterpret_cast<__nv_bfloat16*>(smc);
    __nv_bfloat16* Ws = As + 128*A_STR;
    float*  bias_s = reinterpret_cast<float*>(smc + BIAS_OFF);
    float2* sL     = reinterpret_cast<float2*>(smc + SL_OFF);
    const int tid = threadIdx.x;
    const int w = tid >> 5, lane = tid & 31, g = lane >> 2, tig = lane & 3;
    const int wm = w >> 1, wn = w & 1;
    const int rA0 = wm*32 + g;
    const int nb  = wn*64;
    const int b  = blockIdx.x >> 3;
    const int t0 = (blockIdx.x & 7) * 125;

    for (int i = tid; i < Vz/4; i += 256)
        reinterpret_cast<float4*>(bias_s)[i] = reinterpret_cast<const float4*>(bias)[i];

    for (int e = tid; e < 128*64; e += 256) {
        int row = e >> 6, c = e & 63;
        int t = t0 + row; if (t > Tz-1) t = Tz-1;
        const float4* src = reinterpret_cast<const float4*>(eouts + (size_t)(b*Tz + t)*Hz + c*8);
        float4 v0 = src[0], v1 = src[1];
        __nv_bfloat162 p0 = __floats2bfloat162_rn(v0.x, v0.y);
        __nv_bfloat162 p1 = __floats2bfloat162_rn(v0.z, v0.w);
        __nv_bfloat162 p2 = __floats2bfloat162_rn(v1.x, v1.y);
        __nv_bfloat162 p3 = __floats2bfloat162_rn(v1.z, v1.w);
        uint4 pk = make_uint4(*reinterpret_cast<uint32_t*>(&p0), *reinterpret_cast<uint32_t*>(&p1),
                              *reinterpret_cast<uint32_t*>(&p2), *reinterpret_cast<uint32_t*>(&p3));
        *reinterpret_cast<uint4*>(As + row*A_STR + c*8) = pk;
    }

    float M[4] = {-3e38f,-3e38f,-3e38f,-3e38f};
    float S[4] = {0.f,0.f,0.f,0.f};
    float lsev[4];

    #pragma unroll 1
    for (int nc = 0; nc < 17; nc++) {
        if (nc == 16) {
            if (tig == 0) {
                #pragma unroll
                for (int i = 0; i < 4; i++)
                    sL[wn*128 + rA0 + 8*i] = make_float2(M[i], S[i]);
            }
            __syncthreads();
            #pragma unroll
            for (int i = 0; i < 4; i++) {
                float2 o = sL[(wn^1)*128 + rA0 + 8*i];
                float mn = fmaxf(M[i], o.x);
                float ss = S[i]*__expf(M[i]-mn) + o.y*__expf(o.x-mn);
                lsev[i] = mn + __logf(ss);
            }
        }
        const __nv_bfloat16* wsrc = (nc < 16) ? (g_Wbf + (size_t)(nc*128)*Hz)
                                              : (g_Wlab + (size_t)b*128*Hz);
        uint2 rg[8];
        #pragma unroll
        for (int q = 0; q < 8; q++) {
            int e = tid + q*256; int row = e >> 4, c = e & 15;
            rg[q] = *reinterpret_cast<const uint2*>(wsrc + (size_t)row*Hz + c*4);
        }
        #pragma unroll
        for (int q = 0; q < 8; q++) {
            int e = tid + q*256; int row = e >> 4, c = e & 15;
            *reinterpret_cast<uint2*>(Ws + row*W_STR + c*4) = rg[q];
        }
        __syncthreads();

        float acc[2][8][4];
        #pragma unroll
        for (int mt = 0; mt < 2; mt++)
            #pragma unroll
            for (int nt = 0; nt < 8; nt++) {
                acc[mt][nt][0]=0.f; acc[mt][nt][1]=0.f; acc[mt][nt][2]=0.f; acc[mt][nt][3]=0.f;
            }

        #pragma unroll 1
        for (int kc = 0; kc < 8; kc++) {
            if (kc < 7) {
                #pragma unroll
                for (int q = 0; q < 8; q++) {
                    int e = tid + q*256; int row = e >> 4, c = e & 15;
                    rg[q] = *reinterpret_cast<const uint2*>(wsrc + (size_t)row*Hz + (kc+1)*64 + c*4);
                }
            }
            const __nv_bfloat16* Wb = Ws + (kc & 1) * (128*W_STR);
            #pragma unroll
            for (int ks = 0; ks < 4; ks++) {
                const int kk = kc*64 + ks*16;
                uint32_t a0[2], a1[2], a2[2], a3[2];
                #pragma unroll
                for (int mt = 0; mt < 2; mt++) {
                    const int R = rA0 + 16*mt;
                    a0[mt] = *reinterpret_cast<const uint32_t*>(As + R*A_STR + kk + 2*tig);
                    a1[mt] = *reinterpret_cast<const uint32_t*>(As + (R+8)*A_STR + kk + 2*tig);
                    a2[mt] = *reinterpret_cast<const uint32_t*>(As + R*A_STR + kk + 8 + 2*tig);
                    a3[mt] = *reinterpret_cast<const uint32_t*>(As + (R+8)*A_STR + kk + 8 + 2*tig);
                }
                #pragma unroll
                for (int nt = 0; nt < 8; nt++) {
                    uint32_t b0 = *reinterpret_cast<const uint32_t*>(Wb + (nb+nt*8+g)*W_STR + ks*16 + 2*tig);
                    uint32_t b1 = *reinterpret_cast<const uint32_t*>(Wb + (nb+nt*8+g)*W_STR + ks*16 + 8 + 2*tig);
                    mma16816(acc[0][nt], a0[0], a1[0], a2[0], a3[0], b0, b1);
                    mma16816(acc[1][nt], a0[1], a1[1], a2[1], a3[1], b0, b1);
                }
            }
            __syncthreads();
            if (kc < 7) {
                __nv_bfloat16* Wd = Ws + ((kc+1) & 1) * (128*W_STR);
                #pragma unroll
                for (int q = 0; q < 8; q++) {
                    int e = tid + q*256; int row = e >> 4, c = e & 15;
                    *reinterpret_cast<uint2*>(Wd + row*W_STR + c*4) = rg[q];
                }
                __syncthreads();
            }
        }

        if (nc < 16) {
            float bm[4] = {-3e38f,-3e38f,-3e38f,-3e38f};
            #pragma unroll
            for (int nt = 0; nt < 8; nt++) {
                int c0 = nc*128 + nb + nt*8 + 2*tig;
                float bb0 = bias_s[c0], bb1 = bias_s[c0+1];
                #pragma unroll
                for (int mt = 0; mt < 2; mt++) {
                    acc[mt][nt][0]+=bb0; acc[mt][nt][1]+=bb1;
                    acc[mt][nt][2]+=bb0; acc[mt][nt][3]+=bb1;
                    bm[2*mt]   = fmaxf(bm[2*mt],   fmaxf(acc[mt][nt][0], acc[mt][nt][1]));
                    bm[2*mt+1] = fmaxf(bm[2*mt+1], fmaxf(acc[mt][nt][2], acc[mt][nt][3]));
                }
            }
            float bs[4] = {0.f,0.f,0.f,0.f};
            #pragma unroll
            for (int nt = 0; nt < 8; nt++)
                #pragma unroll
                for (int mt = 0; mt < 2; mt++) {
                    bs[2*mt]   += __expf(acc[mt][nt][0]-bm[2*mt])   + __expf(acc[mt][nt][1]-bm[2*mt]);
                    bs[2*mt+1] += __expf(acc[mt][nt][2]-bm[2*mt+1]) + __expf(acc[mt][nt][3]-bm[2*mt+1]);
                }
            #pragma unroll
            for (int off = 1; off <= 2; off <<= 1) {
                #pragma unroll
                for (int i = 0; i < 4; i++) {
                    float mo = __shfl_xor_sync(0xffffffffu, bm[i], off);
                    float so = __shfl_xor_sync(0xffffffffu, bs[i], off);
                    float mn = fmaxf(bm[i], mo);
                    bs[i] = bs[i]*__expf(bm[i]-mn) + so*__expf(mo-mn); bm[i] = mn;
                }
            }
            #pragma unroll
            for (int i = 0; i < 4; i++) {
                float mn = fmaxf(M[i], bm[i]);
                S[i] = S[i]*__expf(M[i]-mn) + bs[i]*__expf(bm[i]-mn); M[i] = mn;
            }
        } else {
            #pragma unroll
            for (int i = 0; i < 4; i++) {
                int R = rA0 + 8*i;
                int t = t0 + R; if (t > Tz-1) t = Tz-1;
                float* ptr = g_lab + (size_t)(b*Tz + t)*NLAB;
                const int mt = i >> 1, q = (i & 1)*2;
                #pragma unroll
                for (int nt = 0; nt < 8; nt++) {
                    int c0 = nb + nt*8 + 2*tig;
                    if (c0 < NLAB)
                        ptr[c0]   = __expf(acc[mt][nt][q]   + g_blab[b*128 + c0]   - lsev[i] + CCOMP);
                    if (c0+1 < NLAB)
                        ptr[c0+1] = __expf(acc[mt][nt][q+1] + g_blab[b*128 + c0+1] - lsev[i] + CCOMP);
                }
            }
        }
    }
}

// ---------------- kernel 4: CTC DP — forward/backward split (2 CTAs per batch) ----------
__global__ __launch_bounds__(224) void k_dp(const int* __restrict__ ys,
                                            const int* __restrict__ elens,
                                            const int* __restrict__ ylens) {
    __shared__ float sA[2][224];
    __shared__ int   sE[2][8];
    __shared__ int   sM[2][8];
    const int SENT = -(1 << 29);
    const int b = blockIdx.x >> 1;
    const int dir = blockIdx.x & 1;
    const int tid = threadIdx.x, w = tid >> 5, lane = tid & 31;
    const int elen = elens[b], ylen = ylens[b];
    const int smax = 2*ylen + 1;
    const int Tm = (elen - 1) >> 1;
    const float* lab = g_lab + (size_t)b*Tz*NLAB;

    if (dir == 0) {
        // ======================= FORWARD: alpha_0 .. alpha_Tm =======================
        const int s0 = 32*w - 32 + 2*lane;
        const int s1 = s0 + 1;
        const bool v0 = (s0 >= 0) && (s0 < smax);
        const bool v1 = (s1 >= 0) && (s1 < smax);
        const int yidx = (s1 >= 1) ? (s1 >> 1) : 0;
        const int j1c  = min(max(yidx + 1, 0), NLAB - 1);
        bool skip1 = false;
        if (s1 >= 3 && yidx >= 1 && yidx <= Lz - 1)
            skip1 = (ys[b*Lz + yidx] != ys[b*Lz + yidx - 1]);

        float r0 = (v0 && s0 == 0) ? __ldg(lab + 0) : 0.f;
        float r1 = (v1 && s1 == 1) ? __ldg(lab + 1) : 0.f;

        float pB[8], p1[8];
        #pragma unroll
        for (int d = 0; d < 8; d++) {
            int tt = 1 + d; if (tt > Tm) tt = Tm;
            const float* q = lab + (size_t)tt * NLAB;
            pB[d] = __ldg(q);
            p1[d] = __ldg(q + j1c);
        }

        int Ew = 0, buf = 0;
        int t = 1;
        while (t <= Tm) {
            const int rem = Tm - t + 1;
            if (rem >= 8) {
                #pragma unroll
                for (int i = 0; i < 8; i++) {
                    float r1m = __shfl_up_sync(0xffffffffu, r1, 1);
                    if (lane == 0) r1m = 0.f;
                    float n0 = (r0 + r1m) * pB[i];
                    float x2 = skip1 ? r1m : 0.f;
                    float n1 = (r1 + r0 + x2) * p1[i];
                    r0 = v0 ? n0 : 0.f;
                    r1 = v1 ? n1 : 0.f;
                    int tn = t + i + 8; if (tn > Tm) tn = Tm;
                    const float* q = lab + (size_t)tn * NLAB;
                    pB[i] = __ldg(q);
                    p1[i] = __ldg(q + j1c);
                }
                t += 8;
            } else {
                #pragma unroll
                for (int i = 0; i < 8; i++) {
                    if (i < rem) {
                        float r1m = __shfl_up_sync(0xffffffffu, r1, 1);
                        if (lane == 0) r1m = 0.f;
                        float n0 = (r0 + r1m) * pB[i];
                        float x2 = skip1 ? r1m : 0.f;
                        float n1 = (r1 + r0 + x2) * p1[i];
                        r0 = v0 ? n0 : 0.f;
                        r1 = v1 ? n1 : 0.f;
                    }
                }
                t += rem;
            }
            uint32_t lmu;
            {
                float lmf = fmaxf(r0, r1);
                asm volatile("redux.sync.max.u32 %0, %1, 0xffffffff;"
                             : "=r"(lmu) : "r"(__float_as_uint(lmf)));
            }
            if (lane >= 16) { sA[buf][s0] = r0; sA[buf][s1] = r1; }
            if (lane == 0) {
                sE[buf][w] = Ew;
                sM[buf][w] = (lmu != 0u)
                    ? (Ew + (int)((lmu >> 23) & 0xFFu) - 127)
                    : SENT;
            }
            __syncthreads();
            const int eown = sM[buf][w];
            const int enbr = (w > 0) ? sM[buf][w-1] : SENT;
            const int Enbr_old = (w > 0) ? sE[buf][w-1] : 0;
            const int etop = (eown > enbr) ? eown : enbr;
            if (etop > SENT) {
                const int Enew = etop - 30;
                int kk = Ew - Enew;
                float h0 = r0, h1 = r1;
                if (lane < 16 && w > 0) {
                    h0 = sA[buf][s0]; h1 = sA[buf][s1]; kk = Enbr_old - Enew;
                }
                const int k1 = kk >> 1, k2 = kk - (kk >> 1);
                const float f1 = exp2i(k1), f2 = exp2i(k2);
                r0 = h0 * f1 * f2;
                r1 = h1 * f1 * f2;
                Ew = Enew;
            } else {
                if (lane < 16 && w > 0) { r0 = sA[buf][s0]; r1 = sA[buf][s1]; }
            }
            buf ^= 1;
        }
        if (lane >= 16) { g_fa[b*224 + s0] = r0; g_fa[b*224 + s1] = r1; }
        if (lane == 0) g_faE[b*8 + w] = Ew;
    } else {
        // ======================= BACKWARD: beta_{elen-1} .. beta_Tm =======================
        const int P  = 16*w + lane;
        const int s0b = 2*P, s1b = s0b + 1;
        const bool v0 = (s0b < smax);
        const bool v1 = (s1b < smax);
        const int jc = min(P + 1, NLAB - 1);
        bool skn = false;
        if (P <= Lz - 2)
            skn = (ys[b*Lz + P + 1] != ys[b*Lz + P]);

        float b0 = (P == ylen)     ? 1.f : 0.f;
        float b1 = (P == ylen - 1) ? 1.f : 0.f;
        if (!v0) b0 = 0.f;
        if (!v1) b1 = 0.f;

        const int nsteps = elen - 1 - Tm;
        float pB[8], p1[8];
        #pragma unroll
        for (int d = 0; d < 8; d++) {
            int tt = elen - 1 - d; if (tt < 0) tt = 0;
            const float* q = lab + (size_t)tt * NLAB;
            pB[d] = __ldg(q);
            p1[d] = __ldg(q + jc);
        }

        int Ew = 0, buf = 0;
        int done = 0;
        while (done < nsteps) {
            const int rem = nsteps - done;
            if (rem >= 8) {
                #pragma unroll
                for (int i = 0; i < 8; i++) {
                    float z = b1 * p1[i];
                    float b0s = __shfl_down_sync(0xffffffffu, b0, 1);
                    float zs  = __shfl_down_sync(0xffffffffu, z, 1);
                    if (lane == 31) { b0s = 0.f; zs = 0.f; }
                    float n0 = b0 * pB[i] + z;
                    float n1 = z + pB[i] * b0s + (skn ? zs : 0.f);
                    b0 = v0 ? n0 : 0.f;
                    b1 = v1 ? n1 : 0.f;
                    int tn = elen - 1 - (done + i) - 8; if (tn < 0) tn = 0;
                    const float* q = lab + (size_t)tn * NLAB;
                    pB[i] = __ldg(q);
                    p1[i] = __ldg(q + jc);
                }
                done += 8;
            } else {
                #pragma unroll
                for (int i = 0; i < 8; i++) {
                    if (i < rem) {
                        float z = b1 * p1[i];
                        float b0s = __shfl_down_sync(0xffffffffu, b0, 1);
                        float zs  = __shfl_down_sync(0xffffffffu, z, 1);
                        if (lane == 31) { b0s = 0.f; zs = 0.f; }
                        float n0 = b0 * pB[i] + z;
                        float n1 = z + pB[i] * b0s + (skn ? zs : 0.f);
                        b0 = v0 ? n0 : 0.f;
                        b1 = v1 ? n1 : 0.f;
                    }
                }
                done += rem;
            }
            uint32_t lmu;
            {
                float lmf = fmaxf(b0, b1);
                asm volatile("redux.sync.max.u32 %0, %1, 0xffffffff;"
                             : "=r"(lmu) : "r"(__float_as_uint(lmf)));
            }
            if (lane < 16) { sA[buf][s0b] = b0; sA[buf][s1b] = b1; }
            if (lane == 0) {
                sE[buf][w] = Ew;
                sM[buf][w] = (lmu != 0u)
                    ? (Ew + (int)((lmu >> 23) & 0xFFu) - 127)
                    : SENT;
            }
            __syncthreads();
            const int eown = sM[buf][w];
            const int enbr = (w < 6) ? sM[buf][w+1] : SENT;
            const int Enbr_old = (w < 6) ? sE[buf][w+1] : 0;
            const int etop = (eown > enbr) ? eown : enbr;
            if (etop > SENT) {
                const int Enew = etop - 30;
                int kk = Ew - Enew;
                float h0 = b0, h1 = b1;
                if (lane >= 16 && w < 6) {
                    h0 = sA[buf][s0b]; h1 = sA[buf][s1b]; kk = Enbr_old - Enew;
                }
                const int k1 = kk >> 1, k2 = kk - (kk >> 1);
                const float f1 = exp2i(k1), f2 = exp2i(k2);
                b0 = h0 * f1 * f2;
                b1 = h1 * f1 * f2;
                Ew = Enew;
            } else {
                if (lane >= 16 && w < 6) { b0 = sA[buf][s0b]; b1 = sA[buf][s1b]; }
            }
            buf ^= 1;
        }
        if (lane < 16) { g_ba[b*224 + s0b] = b0; g_ba[b*224 + s1b] = b1; }
        if (lane == 0) g_baE[b*8 + w] = Ew;
    }
}

// ---------------- kernel 5: per-batch LOG-DOMAIN combine (one block per batch) ----------
// L_s = log(alpha_Tm(s)) + log(beta_Tm(s)) + (Ea+Eb)*ln2; deterministic tree LSE.
__global__ __launch_bounds__(256) void k_comb(const int* __restrict__ elens,
                                              const int* __restrict__ ylens) {
    __shared__ float sm[256];
    const int b = blockIdx.x;
    const int s = threadIdx.x;
    const int elen = elens[b], ylen = ylens[b];
    const int smax = 2*ylen + 1;
    float L = -3e38f;
    if (s < smax) {
        float a  = g_fa[b*224 + s];
        float bt = g_ba[b*224 + s];
        if (a > 0.f && bt > 0.f) {
            int Ea = g_faE[b*8 + (s >> 5)];
            int Eb = g_baE[b*8 + ((s >> 1) >> 4)];
            L = __logf(a) + __logf(bt) + (float)(Ea + Eb) * LN2F;
        }
    }
    sm[s] = L;
    __syncthreads();
    #pragma unroll
    for (int off = 128; off >= 1; off >>= 1) {
        if (s < off) sm[s] = fmaxf(sm[s], sm[s + off]);
        __syncthreads();
    }
    const float mx = sm[0];
    __syncthreads();
    sm[s] = (L > -1e37f) ? __expf(L - mx) : 0.f;
    __syncthreads();
    #pragma unroll
    for (int off = 128; off >= 1; off >>= 1) {
        if (s < off) sm[s] = sm[s] + sm[s + off];
        __syncthreads();
    }
    if (s == 0) {
        float loss;
        if (mx < -1e37f) loss = 1e30f;                       // sum == 0 -> +inf analogue
        else loss = CCOMP * (float)elen - (mx + __logf(sm[0]));
        g_lossb[b] = (loss < -0.5f*NEGINF) ? loss : 0.f;     // zero_infinity
    }
}

// ---------------- kernel 6: deterministic finalize ----------------
__global__ void k_final(float* __restrict__ out) {
    if (threadIdx.x == 0 && blockIdx.x == 0) {
        float s = 0.f;
        for (int b = 0; b < Bz; b++) s += g_lossb[b];
        out[0] = s / (float)Bz;
    }
}

// ---------------- entry ----------------
extern "C" void kernel_launch(void* const* d_in, const int* in_sizes, int n_in,
                              void* d_out, int out_size) {
    const float* eouts = (const float*)d_in[0];
    const float* W     = (const float*)d_in[1];
    const float* bias  = (const float*)d_in[2];
    const int*   ys    = (const int*)d_in[3];
    const int*   elens = (const int*)d_in[4];
    const int*   ylens = (const int*)d_in[5];
    float* out = (float*)d_out;

    cudaFuncSetAttribute(k_main, cudaFuncAttributeMaxDynamicSharedMemorySize, MAIN_SMEM);

    k_convertW<<<256, 256>>>(W);
    k_gather<<<Bz*128, 64>>>(bias, ys);
    k_main<<<Bz*8, 256, MAIN_SMEM>>>(eouts, bias);
    k_dp<<<Bz*2, 224>>>(ys, elens, ylens);
    k_comb<<<Bz, 256>>>(elens, ylens);
    k_final<<<1, 32>>>(out);
}